// round 2
// baseline (speedup 1.0000x reference)
#include <cuda_runtime.h>

#define NB 8
#define T 16
#define C 256
#define CM 64
#define AA 32
#define HW 784
#define HWC (HW*C)
#define NSPLIT 4
#define PS (HW/NSPLIT)   /* 196 */

// Scratch (allocation-free rule: __device__ globals)
__device__ float g_partial[NB*T*NSPLIT*C];   // 512 KB
__device__ float g_theta[NB*T*C];
__device__ float g_kern[NB*3*C];             // [b][k][c]
__device__ float g_act[NB*T*C];              // [b][t][c]

// ---------------- K1: spatial partial sums (reads x fully) ----------------
__global__ void k_partial(const float* __restrict__ x) {
    int n = blockIdx.x, s = blockIdx.y, c = threadIdx.x;
    const float* xp = x + (size_t)n*HWC + (size_t)s*PS*C + c;
    float a0 = 0.f, a1 = 0.f, a2 = 0.f, a3 = 0.f;
    #pragma unroll 7
    for (int p = 0; p < PS; p += 4) {
        a0 += xp[(size_t)(p+0)*C];
        a1 += xp[(size_t)(p+1)*C];
        a2 += xp[(size_t)(p+2)*C];
        a3 += xp[(size_t)(p+3)*C];
    }
    g_partial[(n*NSPLIT + s)*C + c] = (a0 + a1) + (a2 + a3);
}

// ---------------- K2: finalize theta + global branch (adaptive kernel) ----
__global__ void k_global(const float* __restrict__ w1, const float* __restrict__ gam,
                         const float* __restrict__ bet, const float* __restrict__ mean,
                         const float* __restrict__ var, const float* __restrict__ w2) {
    int b = blockIdx.x, c = threadIdx.x;
    float th[T];
    #pragma unroll
    for (int t = 0; t < T; t++) {
        int n = b*T + t;
        float s = 0.f;
        #pragma unroll
        for (int ss = 0; ss < NSPLIT; ss++) s += g_partial[(n*NSPLIT + ss)*C + c];
        th[t] = s * (1.0f/(float)HW);
        g_theta[n*C + c] = th[t];
    }
    float lg0 = 0.f, lg1 = 0.f, lg2 = 0.f;
    #pragma unroll 4
    for (int a = 0; a < AA; a++) {
        float g = 0.f;
        #pragma unroll
        for (int t = 0; t < T; t++) g += th[t] * w1[t*AA + a];
        float inv = rsqrtf(var[a] + 1e-3f);
        g = (g - mean[a]) * (gam[a] * inv) + bet[a];
        g = fmaxf(g, 0.f);
        lg0 += g * w2[a*3 + 0];
        lg1 += g * w2[a*3 + 1];
        lg2 += g * w2[a*3 + 2];
    }
    float m = fmaxf(lg0, fmaxf(lg1, lg2));
    float e0 = expf(lg0 - m), e1 = expf(lg1 - m), e2 = expf(lg2 - m);
    float inv = 1.f/(e0 + e1 + e2);
    g_kern[(b*3 + 0)*C + c] = e0*inv;
    g_kern[(b*3 + 1)*C + c] = e1*inv;
    g_kern[(b*3 + 2)*C + c] = e2*inv;
}

// ---------------- K3: local branch conv(3,256->64) -> bn/relu -> conv(1,64->256) -> sigmoid
// one block per (t, b): keeps the tiny conv work spread over 128 blocks
__global__ void k_local(const float* __restrict__ w1, const float* __restrict__ gam,
                        const float* __restrict__ bet, const float* __restrict__ mean,
                        const float* __restrict__ var, const float* __restrict__ w2) {
    int t = blockIdx.x, b = blockIdx.y, tid = threadIdx.x;
    __shared__ float th_s[3*C];
    __shared__ float red[256];
    __shared__ float l_s[CM];
    #pragma unroll
    for (int dt = 0; dt < 3; dt++) {
        int tt = t + dt - 1;
        th_s[dt*C + tid] = (tt >= 0 && tt < T) ? g_theta[(b*T + tt)*C + tid] : 0.f;
    }
    __syncthreads();
    int m = tid & 63, part = tid >> 6;  // 4 partial slices over the 3*256 reduction
    float acc = 0.f;
    #pragma unroll 8
    for (int i = 0; i < 192; i++) {
        int j = part*192 + i;                 // j = dt*256 + c
        acc += th_s[j] * w1[j*CM + m];
    }
    red[tid] = acc;
    __syncthreads();
    if (tid < CM) {
        float v = red[tid] + red[tid+64] + red[tid+128] + red[tid+192];
        float inv = rsqrtf(var[tid] + 1e-3f);
        v = (v - mean[tid]) * (gam[tid] * inv) + bet[tid];
        l_s[tid] = fmaxf(v, 0.f);
    }
    __syncthreads();
    float o = 0.f;
    #pragma unroll 8
    for (int mm = 0; mm < CM; mm++) o += l_s[mm] * w2[mm*C + tid];
    g_act[(b*T + t)*C + tid] = 1.f/(1.f + expf(-o));
}

// ---------------- K4: fused gate + adaptive temporal conv (the heavy pass) --
// y[b,c,t,p] = sum_k kern[b,c,k]*act[b,c,t-1+k]*x[b,c,t-1+k,p]
// coef[t][k][c] staged in 48KB smem; x streamed once via 3-reg rotation over t.
__global__ void k_agg(const float* __restrict__ x, float* __restrict__ y) {
    int b = blockIdx.y, tid = threadIdx.x;
    int c4 = tid & 63, pi = tid >> 6;
    int p = blockIdx.x*4 + pi;
    __shared__ float coef[T*3*C];  // exactly 48 KB
    float k0 = g_kern[(b*3 + 0)*C + tid];
    float k1 = g_kern[(b*3 + 1)*C + tid];
    float k2 = g_kern[(b*3 + 2)*C + tid];
    // boundary (t,k) pairs whose source time is out of range:
    coef[(0*3 + 0)*C + tid]  = 0.f;
    coef[(15*3 + 2)*C + tid] = 0.f;
    #pragma unroll
    for (int ts = 0; ts < T; ts++) {
        float a = g_act[(b*T + ts)*C + tid];
        #pragma unroll
        for (int k = 0; k < 3; k++) {
            int t = ts + 1 - k;                 // output time using source ts with tap k
            if (t >= 0 && t < T) {
                float kk = (k == 0) ? k0 : ((k == 1) ? k1 : k2);
                coef[(t*3 + k)*C + tid] = kk * a;
            }
        }
    }
    __syncthreads();
    const float4* cs4 = (const float4*)coef;
    size_t base4 = ((size_t)(b*T)*HWC + (size_t)p*C) / 4 + c4;
    const float4* xp = (const float4*)x + base4;
    float4*       yp = (float4*)y + base4;
    const int S4 = HWC/4;
    float4 xm = make_float4(0.f,0.f,0.f,0.f);
    float4 xc = xp[0];
    #pragma unroll
    for (int t = 0; t < T; t++) {
        float4 xn = (t < T-1) ? xp[(size_t)(t+1)*S4] : make_float4(0.f,0.f,0.f,0.f);
        float4 c0 = cs4[(t*3 + 0)*64 + c4];
        float4 c1 = cs4[(t*3 + 1)*64 + c4];
        float4 c2 = cs4[(t*3 + 2)*64 + c4];
        float4 o;
        o.x = c0.x*xm.x + c1.x*xc.x + c2.x*xn.x;
        o.y = c0.y*xm.y + c1.y*xc.y + c2.y*xn.y;
        o.z = c0.z*xm.z + c1.z*xc.z + c2.z*xn.z;
        o.w = c0.w*xm.w + c1.w*xc.w + c2.w*xn.w;
        yp[(size_t)t*S4] = o;
        xm = xc; xc = xn;
    }
}

extern "C" void kernel_launch(void* const* d_in, const int* in_sizes, int n_in,
                              void* d_out, int out_size) {
    const float* x       = (const float*)d_in[0];
    const float* gw1     = (const float*)d_in[1];
    const float* ggamma  = (const float*)d_in[2];
    const float* gbeta   = (const float*)d_in[3];
    const float* gmean   = (const float*)d_in[4];
    const float* gvar    = (const float*)d_in[5];
    const float* gw2     = (const float*)d_in[6];
    const float* lw1     = (const float*)d_in[7];
    const float* lgamma  = (const float*)d_in[8];
    const float* lbeta   = (const float*)d_in[9];
    const float* lmean   = (const float*)d_in[10];
    const float* lvar    = (const float*)d_in[11];
    const float* lw2     = (const float*)d_in[12];
    float* y = (float*)d_out;

    k_partial<<<dim3(NB*T, NSPLIT), 256>>>(x);
    k_global <<<NB, 256>>>(gw1, ggamma, gbeta, gmean, gvar, gw2);
    k_local  <<<dim3(T, NB), 256>>>(lw1, lgamma, lbeta, lmean, lvar, lw2);
    k_agg    <<<dim3(HW/4, NB), 256>>>(x, y);
}

// round 3
// speedup vs baseline: 1.2488x; 1.2488x over previous
#include <cuda_runtime.h>

#define NB 8
#define T 16
#define C 256
#define CM 64
#define AA 32
#define HW 784
#define HWC (HW*C)
#define NSPLIT 4
#define PS (HW/NSPLIT)      /* 196 spatial rows per segment */
#define NSEG (NSPLIT*4)     /* 16 partial slots per frame (4 segs x 4 pi-rows) */

// Scratch (allocation-free rule: __device__ globals)
__device__ float g_partial[NB*T*NSEG*C];   // 2 MB
__device__ float g_kern[NB*3*C];           // [b][k][c]
__device__ float g_act[NB*T*C];            // [b][t][c]

// ---------------- K1: spatial partial sums, float4 loads ----------------
__global__ void k_partial(const float4* __restrict__ x4) {
    int n = blockIdx.x, s = blockIdx.y, tid = threadIdx.x;
    int c4 = tid & 63, pi = tid >> 6;
    const float4* xp = x4 + (size_t)n*(HWC/4) + (size_t)(s*PS + pi)*64 + c4;
    float4 a0 = make_float4(0,0,0,0), a1 = a0, a2 = a0, a3 = a0;
    #pragma unroll 4
    for (int i = 0; i < 48; i += 4) {
        float4 v0 = xp[(size_t)(i+0)*256];
        float4 v1 = xp[(size_t)(i+1)*256];
        float4 v2 = xp[(size_t)(i+2)*256];
        float4 v3 = xp[(size_t)(i+3)*256];
        a0.x += v0.x; a0.y += v0.y; a0.z += v0.z; a0.w += v0.w;
        a1.x += v1.x; a1.y += v1.y; a1.z += v1.z; a1.w += v1.w;
        a2.x += v2.x; a2.y += v2.y; a2.z += v2.z; a2.w += v2.w;
        a3.x += v3.x; a3.y += v3.y; a3.z += v3.z; a3.w += v3.w;
    }
    {   // iteration 48 (49 rows per thread total)
        float4 v = xp[(size_t)48*256];
        a0.x += v.x; a0.y += v.y; a0.z += v.z; a0.w += v.w;
    }
    float4 r;
    r.x = (a0.x + a1.x) + (a2.x + a3.x);
    r.y = (a0.y + a1.y) + (a2.y + a3.y);
    r.z = (a0.z + a1.z) + (a2.z + a3.z);
    r.w = (a0.w + a1.w) + (a2.w + a3.w);
    ((float4*)g_partial)[(size_t)(n*NSEG + s*4 + pi)*64 + c4] = r;
}

// ---------------- K2: fused branch kernel ----------------
// blocks [0, NB*T): local branch (per b,t) -> g_act
// blocks [NB*T, NB*T+NB): global branch (per b)  -> g_kern
__global__ void k_branch(const float* __restrict__ gw1, const float* __restrict__ ggam,
                         const float* __restrict__ gbet, const float* __restrict__ gmean,
                         const float* __restrict__ gvar, const float* __restrict__ gw2,
                         const float* __restrict__ lw1, const float* __restrict__ lgam,
                         const float* __restrict__ lbet, const float* __restrict__ lmean,
                         const float* __restrict__ lvar, const float* __restrict__ lw2) {
    int bid = blockIdx.x, tid = threadIdx.x;
    if (bid < NB*T) {
        // ---- local branch: conv(3,256->64) -> bn/relu -> conv(1,64->256) -> sigmoid
        int b = bid / T, t = bid % T;
        __shared__ float th_s[3*C];
        __shared__ float red[256];
        __shared__ float l_s[CM];
        #pragma unroll
        for (int dt = 0; dt < 3; dt++) {
            int tt = t + dt - 1;
            float s = 0.f;
            if (tt >= 0 && tt < T) {
                #pragma unroll
                for (int ss = 0; ss < NSEG; ss++)
                    s += g_partial[(size_t)((b*T + tt)*NSEG + ss)*C + tid];
                s *= (1.0f/(float)HW);
            }
            th_s[dt*C + tid] = s;
        }
        __syncthreads();
        int m = tid & 63, part = tid >> 6;
        float acc = 0.f;
        #pragma unroll 8
        for (int i = 0; i < 192; i++) {
            int j = part*192 + i;                 // j = dt*256 + c
            acc += th_s[j] * lw1[j*CM + m];
        }
        red[tid] = acc;
        __syncthreads();
        if (tid < CM) {
            float v = red[tid] + red[tid+64] + red[tid+128] + red[tid+192];
            float inv = rsqrtf(lvar[tid] + 1e-3f);
            v = (v - lmean[tid]) * (lgam[tid] * inv) + lbet[tid];
            l_s[tid] = fmaxf(v, 0.f);
        }
        __syncthreads();
        float o = 0.f;
        #pragma unroll 8
        for (int mm = 0; mm < CM; mm++) o += l_s[mm] * lw2[mm*C + tid];
        g_act[(b*T + t)*C + tid] = 1.f/(1.f + expf(-o));
    } else {
        // ---- global branch: Dense(T->32) -> bn/relu -> Dense(32->3) -> softmax
        int b = bid - NB*T, c = tid;
        float th[T];
        #pragma unroll
        for (int t = 0; t < T; t++) {
            float s = 0.f;
            #pragma unroll
            for (int ss = 0; ss < NSEG; ss++)
                s += g_partial[(size_t)((b*T + t)*NSEG + ss)*C + c];
            th[t] = s * (1.0f/(float)HW);
        }
        float lg0 = 0.f, lg1 = 0.f, lg2 = 0.f;
        #pragma unroll 4
        for (int a = 0; a < AA; a++) {
            float g = 0.f;
            #pragma unroll
            for (int t = 0; t < T; t++) g += th[t] * gw1[t*AA + a];
            float inv = rsqrtf(gvar[a] + 1e-3f);
            g = (g - gmean[a]) * (ggam[a] * inv) + gbet[a];
            g = fmaxf(g, 0.f);
            lg0 += g * gw2[a*3 + 0];
            lg1 += g * gw2[a*3 + 1];
            lg2 += g * gw2[a*3 + 2];
        }
        float mx = fmaxf(lg0, fmaxf(lg1, lg2));
        float e0 = expf(lg0 - mx), e1 = expf(lg1 - mx), e2 = expf(lg2 - mx);
        float inv = 1.f/(e0 + e1 + e2);
        g_kern[(b*3 + 0)*C + c] = e0*inv;
        g_kern[(b*3 + 1)*C + c] = e1*inv;
        g_kern[(b*3 + 2)*C + c] = e2*inv;
    }
}

// ---------------- K3: fused gate + adaptive temporal conv (heavy pass) --
// y[b,c,t,p] = sum_k kern[b,c,k]*act[b,c,t-1+k]*x[b,c,t-1+k,p]
// Reversed block order to hit the L2-resident tail of x left by k_partial;
// streaming stores (__stcs) so y writes don't evict x from L2.
__global__ void k_agg(const float* __restrict__ x, float* __restrict__ y) {
    int tid = threadIdx.x;
    int b  = (NB - 1) - blockIdx.y;                 // reversed
    int pb = (gridDim.x - 1) - blockIdx.x;          // reversed
    int c4 = tid & 63, pi = tid >> 6;
    int p = pb*4 + pi;
    __shared__ float coef[T*3*C];  // 48 KB
    float k0 = g_kern[(b*3 + 0)*C + tid];
    float k1 = g_kern[(b*3 + 1)*C + tid];
    float k2 = g_kern[(b*3 + 2)*C + tid];
    coef[(0*3 + 0)*C + tid]  = 0.f;
    coef[(15*3 + 2)*C + tid] = 0.f;
    #pragma unroll
    for (int ts = 0; ts < T; ts++) {
        float a = g_act[(b*T + ts)*C + tid];
        #pragma unroll
        for (int k = 0; k < 3; k++) {
            int t = ts + 1 - k;                 // output time sourcing ts with tap k
            if (t >= 0 && t < T) {
                float kk = (k == 0) ? k0 : ((k == 1) ? k1 : k2);
                coef[(t*3 + k)*C + tid] = kk * a;
            }
        }
    }
    __syncthreads();
    const float4* cs4 = (const float4*)coef;
    size_t base4 = ((size_t)(b*T)*HWC + (size_t)p*C) / 4 + c4;
    const float4* xp = (const float4*)x + base4;
    float4*       yp = (float4*)y + base4;
    const int S4 = HWC/4;
    float4 xm = make_float4(0.f,0.f,0.f,0.f);
    float4 xc = xp[0];
    #pragma unroll
    for (int t = 0; t < T; t++) {
        float4 xn = (t < T-1) ? xp[(size_t)(t+1)*S4] : make_float4(0.f,0.f,0.f,0.f);
        float4 c0 = cs4[(t*3 + 0)*64 + c4];
        float4 c1 = cs4[(t*3 + 1)*64 + c4];
        float4 c2 = cs4[(t*3 + 2)*64 + c4];
        float4 o;
        o.x = c0.x*xm.x + c1.x*xc.x + c2.x*xn.x;
        o.y = c0.y*xm.y + c1.y*xc.y + c2.y*xn.y;
        o.z = c0.z*xm.z + c1.z*xc.z + c2.z*xn.z;
        o.w = c0.w*xm.w + c1.w*xc.w + c2.w*xn.w;
        __stcs(yp + (size_t)t*S4, o);
        xm = xc; xc = xn;
    }
}

extern "C" void kernel_launch(void* const* d_in, const int* in_sizes, int n_in,
                              void* d_out, int out_size) {
    const float* x       = (const float*)d_in[0];
    const float* gw1     = (const float*)d_in[1];
    const float* ggamma  = (const float*)d_in[2];
    const float* gbeta   = (const float*)d_in[3];
    const float* gmean   = (const float*)d_in[4];
    const float* gvar    = (const float*)d_in[5];
    const float* gw2     = (const float*)d_in[6];
    const float* lw1     = (const float*)d_in[7];
    const float* lgamma  = (const float*)d_in[8];
    const float* lbeta   = (const float*)d_in[9];
    const float* lmean   = (const float*)d_in[10];
    const float* lvar    = (const float*)d_in[11];
    const float* lw2     = (const float*)d_in[12];
    float* y = (float*)d_out;

    k_partial<<<dim3(NB*T, NSPLIT), 256>>>((const float4*)x);
    k_branch <<<NB*T + NB, 256>>>(gw1, ggamma, gbeta, gmean, gvar, gw2,
                                  lw1, lgamma, lbeta, lmean, lvar, lw2);
    k_agg    <<<dim3(HW/4, NB), 256>>>(x, y);
}